// round 1
// baseline (speedup 1.0000x reference)
#include <cuda_runtime.h>
#include <cstdint>

#define BROWS 2048
#define NCOLS 16384
#define KITER 16
#define NTHREADS 1024

// ---- packed f32x2 helpers (Blackwell-only FFMA2/FMUL2/FADD2 path) ----
__device__ __forceinline__ uint64_t pk2(float lo, float hi) {
    uint64_t r; asm("mov.b64 %0,{%1,%2};" : "=l"(r) : "f"(lo), "f"(hi)); return r;
}
__device__ __forceinline__ void upk2(uint64_t v, float& lo, float& hi) {
    asm("mov.b64 {%0,%1},%2;" : "=f"(lo), "=f"(hi) : "l"(v));
}
__device__ __forceinline__ uint64_t mul2(uint64_t a, uint64_t b) {
    uint64_t r; asm("mul.rn.f32x2 %0,%1,%2;" : "=l"(r) : "l"(a), "l"(b)); return r;
}
__device__ __forceinline__ uint64_t add2(uint64_t a, uint64_t b) {
    uint64_t r; asm("add.rn.f32x2 %0,%1,%2;" : "=l"(r) : "l"(a), "l"(b)); return r;
}
__device__ __forceinline__ uint64_t fma2(uint64_t a, uint64_t b, uint64_t c) {
    uint64_t r; asm("fma.rn.f32x2 %0,%1,%2,%3;" : "=l"(r) : "l"(a), "l"(b), "l"(c)); return r;
}

__global__ void __launch_bounds__(NTHREADS, 1)
subset_op_kernel(const float* __restrict__ scores,
                 const float* __restrict__ gnoise,
                 float* __restrict__ out) {
    const int row = blockIdx.x;
    const int tid = threadIdx.x;
    const size_t base = (size_t)row * NCOLS;

    __shared__ float red[2][33];   // ping-pong: 32 warp partials + broadcast slot

    // ---- load s = scores + g (coalesced float4), 16 elems/thread ----
    float s[16];
#pragma unroll
    for (int i = 0; i < 4; i++) {
        int i4 = tid + i * NTHREADS;
        float4 a = reinterpret_cast<const float4*>(scores + base)[i4];
        float4 b = reinterpret_cast<const float4*>(gnoise + base)[i4];
        s[4*i+0] = a.x + b.x; s[4*i+1] = a.y + b.y;
        s[4*i+2] = a.z + b.z; s[4*i+3] = a.w + b.w;
    }

    const int w = tid >> 5, l = tid & 31;

    // ---- row max (one-time block reduction) ----
    float m = s[0];
#pragma unroll
    for (int i = 1; i < 16; i++) m = fmaxf(m, s[i]);
#pragma unroll
    for (int o = 16; o; o >>= 1) m = fmaxf(m, __shfl_xor_sync(0xffffffffu, m, o));
    if (l == 0) red[0][w] = m;
    __syncthreads();
    if (w == 0) {
        float x = red[0][l];
#pragma unroll
        for (int o = 16; o; o >>= 1) x = fmaxf(x, __shfl_xor_sync(0xffffffffu, x, o));
        if (l == 0) red[0][32] = x;
    }
    __syncthreads();
    const float M = red[0][32];

    // ---- e = exp(s - M); single exp per element for the entire algorithm ----
    uint64_t e2[8], k2[8];
    float lsum = 0.f;
#pragma unroll
    for (int p = 0; p < 8; p++) {
        float e0 = __expf(s[2*p]   - M);
        float e1 = __expf(s[2*p+1] - M);
        e2[p] = pk2(e0, e1);
        k2[p] = 0ULL;
        lsum += e0 + e1;
    }

    const uint64_t NEG1 = 0xBF800000BF800000ULL;  // {-1.0f, -1.0f}

    // ---- K iterations: onehot = e*inv; khot += onehot; e *= (1 - onehot) ----
#pragma unroll 1
    for (int it = 0; it < KITER; it++) {
        // block reduce lsum -> sum (ping-pong smem buffer by iteration parity)
        float v = lsum;
#pragma unroll
        for (int o = 16; o; o >>= 1) v += __shfl_xor_sync(0xffffffffu, v, o);
        float* rb = red[it & 1];
        if (l == 0) rb[w] = v;
        __syncthreads();
        if (w == 0) {
            float x = rb[l];
#pragma unroll
            for (int o = 16; o; o >>= 1) x += __shfl_xor_sync(0xffffffffu, x, o);
            if (l == 0) rb[32] = x;
        }
        __syncthreads();
        const float sum = rb[32];

        // inv slightly < 1/sum guarantees onehot < 1 (replaces the EPS clamp;
        // induced khot error <= ~1e-6 per iteration, far under 1e-3 tolerance)
        const float inv = __fdividef(0.999999f, sum);
        const uint64_t ninv2 = pk2(-inv, -inv);

        uint64_t acc = 0ULL;  // packed {0.f, 0.f}
#pragma unroll
        for (int p = 0; p < 8; p++) {
            uint64_t ohn = mul2(e2[p], ninv2);     // -onehot
            k2[p] = fma2(ohn, NEG1, k2[p]);        // khot += onehot
            e2[p] = fma2(ohn, e2[p], e2[p]);       // e = e*(1 - onehot)
            acc   = add2(acc, e2[p]);              // next-iter partial sum
        }
        float a0, a1; upk2(acc, a0, a1);
        lsum = a0 + a1;
    }

    // ---- store khot (coalesced float4) ----
#pragma unroll
    for (int i = 0; i < 4; i++) {
        float4 v;
        upk2(k2[2*i],   v.x, v.y);
        upk2(k2[2*i+1], v.z, v.w);
        reinterpret_cast<float4*>(out + base)[tid + i * NTHREADS] = v;
    }
}

extern "C" void kernel_launch(void* const* d_in, const int* in_sizes, int n_in,
                              void* d_out, int out_size) {
    const float* scores = (const float*)d_in[0];
    const float* g      = (const float*)d_in[1];
    float* out          = (float*)d_out;
    subset_op_kernel<<<BROWS, NTHREADS>>>(scores, g, out);
}